// round 16
// baseline (speedup 1.0000x reference)
#include <cuda_runtime.h>
#include <cuda_bf16.h>
#include <cuda_fp16.h>
#include <mma.h>
#include <cstdint>
using namespace nvcuda;

#define BATCH 4
#define SEQ   4096
#define HID   256
#define MTOT  (BATCH * SEQ)

__device__ __align__(16) __nv_bfloat16 g_Qh[MTOT * HID];
__device__ __align__(16) __nv_bfloat16 g_Ql[MTOT * HID];
__device__ __align__(16) __nv_bfloat16 g_Kh[MTOT * HID];
__device__ __align__(16) __nv_bfloat16 g_Kl[MTOT * HID];
__device__ __align__(16) __half        g_Vh[MTOT * HID];
__device__ __align__(16) float         g_S [(size_t)BATCH * SEQ * SEQ];   // 256 MB
__device__ __align__(16) __nv_bfloat16 g_Xh[MTOT * HID];
__device__ __align__(16) __nv_bfloat16 g_Xl[MTOT * HID];
__device__ __align__(16) __nv_bfloat16 g_Wth[3 * HID * HID];   // [z][n][k]
__device__ __align__(16) __nv_bfloat16 g_Wtl[3 * HID * HID];
__device__ unsigned g_rmax[MTOT];

__device__ __forceinline__ uint32_t smem_u32(const void* p) {
    uint32_t a;
    asm("{ .reg .u64 t; cvta.to.shared.u64 t, %1; cvt.u32.u64 %0, t; }" : "=r"(a) : "l"(p));
    return a;
}
__device__ __forceinline__ unsigned enc_f(float f) {
    unsigned u = __float_as_uint(f);
    return (u & 0x80000000u) ? ~u : (u | 0x80000000u);
}
__device__ __forceinline__ float dec_f(unsigned e) {
    unsigned u = (e & 0x80000000u) ? (e ^ 0x80000000u) : ~e;
    return __uint_as_float(u);
}
#define CPA(dst, src) \
    asm volatile("cp.async.cg.shared.global [%0], [%1], 16;" :: "r"(dst), "l"(src))
#define CP_COMMIT() asm volatile("cp.async.commit_group;" ::: "memory")
#define CP_WAIT(n)  asm volatile("cp.async.wait_group %0;" :: "n"(n) : "memory")

#define LDSM4(r, a) \
    asm volatile("ldmatrix.sync.aligned.m8n8.x4.shared.b16 {%0,%1,%2,%3}, [%4];" \
        : "=r"((r)[0]), "=r"((r)[1]), "=r"((r)[2]), "=r"((r)[3]) : "r"(a))
#define LDSM4T(r, a) \
    asm volatile("ldmatrix.sync.aligned.m8n8.x4.trans.shared.b16 {%0,%1,%2,%3}, [%4];" \
        : "=r"((r)[0]), "=r"((r)[1]), "=r"((r)[2]), "=r"((r)[3]) : "r"(a))

__device__ __forceinline__ void mma_bf16(float* c, const uint32_t* a, uint32_t b0, uint32_t b1) {
    asm volatile(
        "mma.sync.aligned.m16n8k16.row.col.f32.bf16.bf16.f32 "
        "{%0,%1,%2,%3}, {%4,%5,%6,%7}, {%8,%9}, {%0,%1,%2,%3};"
        : "+f"(c[0]), "+f"(c[1]), "+f"(c[2]), "+f"(c[3])
        : "r"(a[0]), "r"(a[1]), "r"(a[2]), "r"(a[3]), "r"(b0), "r"(b1));
}
__device__ __forceinline__ void mma_fp16(float* c, const uint32_t* a, uint32_t b0, uint32_t b1) {
    asm volatile(
        "mma.sync.aligned.m16n8k16.row.col.f32.f16.f16.f32 "
        "{%0,%1,%2,%3}, {%4,%5,%6,%7}, {%8,%9}, {%0,%1,%2,%3};"
        : "+f"(c[0]), "+f"(c[1]), "+f"(c[2]), "+f"(c[3])
        : "r"(a[0]), "r"(a[1]), "r"(a[2]), "r"(a[3]), "r"(b0), "r"(b1));
}

// ---------------------------------------------------------------------------
// prep_x: split X -> bf16 hi/lo; zero g_rmax.
// ---------------------------------------------------------------------------
__global__ __launch_bounds__(256) void prep_x(const float* __restrict__ X)
{
    int idx = blockIdx.x * 256 + threadIdx.x;          // 1 float4 per thread
    float4 v = *reinterpret_cast<const float4*>(X + (size_t)idx * 4);
    __nv_bfloat16 h0 = __float2bfloat16_rn(v.x);
    __nv_bfloat16 h1 = __float2bfloat16_rn(v.y);
    __nv_bfloat16 h2 = __float2bfloat16_rn(v.z);
    __nv_bfloat16 h3 = __float2bfloat16_rn(v.w);
    __nv_bfloat162* H = reinterpret_cast<__nv_bfloat162*>(g_Xh + (size_t)idx * 4);
    __nv_bfloat162* L = reinterpret_cast<__nv_bfloat162*>(g_Xl + (size_t)idx * 4);
    H[0] = {h0, h1}; H[1] = {h2, h3};
    L[0] = {__float2bfloat16_rn(v.x - __bfloat162float(h0)),
            __float2bfloat16_rn(v.y - __bfloat162float(h1))};
    L[1] = {__float2bfloat16_rn(v.z - __bfloat162float(h2)),
            __float2bfloat16_rn(v.w - __bfloat162float(h3))};
    if (idx < MTOT) g_rmax[idx] = 0u;
}

// ---------------------------------------------------------------------------
// prep_w: split + transpose W -> g_Wth/g_Wtl [z][n][k].
// ---------------------------------------------------------------------------
__global__ __launch_bounds__(256) void prep_w(
    const float* __restrict__ Wq, const float* __restrict__ Wk,
    const float* __restrict__ Wv)
{
    const int z = blockIdx.y, k = blockIdx.x, n = threadIdx.x;
    const float* W = (z == 0) ? Wq : (z == 1) ? Wk : Wv;
    float v = W[k * HID + n];
    __nv_bfloat16 h = __float2bfloat16_rn(v);
    g_Wth[(size_t)z * HID * HID + (size_t)n * HID + k] = h;
    g_Wtl[(size_t)z * HID * HID + (size_t)n * HID + k] =
        __float2bfloat16_rn(v - __bfloat162float(h));
}

// ---------------------------------------------------------------------------
// qkv_tc: bf16x3 tensor-core QKV projection.  (proven)
// ---------------------------------------------------------------------------
#define QT_AH    0
#define QT_AL    10240
#define QT_BH    20480
#define QT_BL    30720
#define QT_STG   40960
#define QT_SMEM  81920

__global__ __launch_bounds__(256, 2) void qkv_tc()
{
    extern __shared__ __align__(1024) char smem[];
    const uint32_t sm32 = smem_u32(smem);
    const int tid = threadIdx.x;
    const int w = tid >> 5;
    const int lane = tid & 31;
    const int mw = w >> 1, dw = w & 1;
    const int m0 = blockIdx.x * 128;
    const int z = blockIdx.y >> 1;
    const int n0 = (blockIdx.y & 1) * 128;

    const char* AhG = (const char*)(g_Xh + (size_t)m0 * HID);
    const char* AlG = (const char*)(g_Xl + (size_t)m0 * HID);
    const char* BhG = (const char*)(g_Wth + (size_t)z * HID * HID + (size_t)n0 * HID);
    const char* BlG = (const char*)(g_Wtl + (size_t)z * HID * HID + (size_t)n0 * HID);

    auto loadchunk = [&](int c) {
        uint32_t base = sm32 + (c & 1) * QT_STG;
        #pragma unroll
        for (int e = 0; e < 2; e++) {
            int idx = e * 256 + tid;
            int row = idx >> 2, col = idx & 3;
            uint32_t so = row * 80 + col * 16;
            size_t   go = (size_t)row * 512 + c * 64 + col * 16;
            CPA(base + QT_AH + so, AhG + go);
            CPA(base + QT_AL + so, AlG + go);
            CPA(base + QT_BH + so, BhG + go);
            CPA(base + QT_BL + so, BlG + go);
        }
    };

    float c[2][8][4];
    #pragma unroll
    for (int m = 0; m < 2; m++)
        #pragma unroll
        for (int n = 0; n < 8; n++)
            #pragma unroll
            for (int j = 0; j < 4; j++) c[m][n][j] = 0.0f;

    const uint32_t a_roff = (uint32_t)((lane & 7) + ((lane & 8) ? 8 : 0)) * 80
                          + ((lane & 16) ? 16 : 0);
    const uint32_t b_roff = (uint32_t)((lane & 7) + ((lane & 16) ? 8 : 0)) * 80
                          + ((lane & 8) ? 16 : 0);

    loadchunk(0);
    CP_COMMIT();
    for (int ch = 0; ch < 8; ch++) {
        CP_WAIT(0);
        __syncthreads();
        if (ch + 1 < 8) { loadchunk(ch + 1); CP_COMMIT(); }
        const uint32_t base = sm32 + (ch & 1) * QT_STG;
        #pragma unroll
        for (int kk = 0; kk < 2; kk++) {
            uint32_t ah[2][4], al[2][4];
            #pragma unroll
            for (int m = 0; m < 2; m++) {
                uint32_t arow = (uint32_t)(mw * 32 + m * 16) * 80 + kk * 32;
                LDSM4(ah[m], base + QT_AH + arow + a_roff);
                LDSM4(al[m], base + QT_AL + arow + a_roff);
            }
            uint32_t bh[8][2], bl[8][2];
            #pragma unroll
            for (int nn = 0; nn < 4; nn++) {
                uint32_t brow = (uint32_t)(dw * 64 + nn * 16) * 80 + kk * 32;
                uint32_t r4[4];
                LDSM4(r4, base + QT_BH + brow + b_roff);
                bh[nn * 2][0] = r4[0]; bh[nn * 2][1] = r4[1];
                bh[nn * 2 + 1][0] = r4[2]; bh[nn * 2 + 1][1] = r4[3];
                LDSM4(r4, base + QT_BL + brow + b_roff);
                bl[nn * 2][0] = r4[0]; bl[nn * 2][1] = r4[1];
                bl[nn * 2 + 1][0] = r4[2]; bl[nn * 2 + 1][1] = r4[3];
            }
            #pragma unroll
            for (int m = 0; m < 2; m++)
                #pragma unroll
                for (int n = 0; n < 8; n++) {
                    mma_bf16(c[m][n], ah[m], bh[n][0], bh[n][1]);
                    mma_bf16(c[m][n], ah[m], bl[n][0], bl[n][1]);
                    mma_bf16(c[m][n], al[m], bh[n][0], bh[n][1]);
                }
        }
    }

    const int qr = lane >> 2;
    const int cg = lane & 3;
    const float s = (z == 0) ? 0.0625f : 1.0f;
    #pragma unroll
    for (int m = 0; m < 2; m++) {
        int row0 = m0 + mw * 32 + m * 16 + qr;
        int colb = n0 + dw * 64 + cg * 2;
        if (z == 2) {
            #pragma unroll
            for (int rr = 0; rr < 2; rr++) {
                __half* Vr = g_Vh + (size_t)(row0 + rr * 8) * HID;
                #pragma unroll
                for (int n = 0; n < 8; n++)
                    *reinterpret_cast<__half2*>(Vr + colb + n * 8) =
                        __floats2half2_rn(c[m][n][rr * 2], c[m][n][rr * 2 + 1]);
            }
        } else {
            __nv_bfloat16* Gh = (z == 0) ? g_Qh : g_Kh;
            __nv_bfloat16* Gl = (z == 0) ? g_Ql : g_Kl;
            #pragma unroll
            for (int rr = 0; rr < 2; rr++) {
                size_t rb = (size_t)(row0 + rr * 8) * HID;
                #pragma unroll
                for (int n = 0; n < 8; n++) {
                    float v0 = c[m][n][rr * 2] * s, v1 = c[m][n][rr * 2 + 1] * s;
                    __nv_bfloat16 h0 = __float2bfloat16_rn(v0);
                    __nv_bfloat16 h1 = __float2bfloat16_rn(v1);
                    *reinterpret_cast<__nv_bfloat162*>(Gh + rb + colb + n * 8) = {h0, h1};
                    *reinterpret_cast<__nv_bfloat162*>(Gl + rb + colb + n * 8) =
                        {__float2bfloat16_rn(v0 - __bfloat162float(h0)),
                         __float2bfloat16_rn(v1 - __bfloat162float(h1))};
                }
            }
        }
    }
}

// ---------------------------------------------------------------------------
// s_body: S = Q K^T (bf16 x3) + per-row max, one 128q x 128k tile.  (proven)
// ---------------------------------------------------------------------------
#define SG_QH    0
#define SG_QL    10240
#define SG_KH    20480
#define SG_KL    30720
#define SG_STG   40960
#define SG_SMEM  81920

__device__ __forceinline__ void s_body(char* smem, int b, int q0, int k0)
{
    const uint32_t sm32 = smem_u32(smem);
    const int tid = threadIdx.x;
    const int w = tid >> 5;
    const int lane = tid & 31;
    const int mw = w >> 1, dw = w & 1;

    const char* QhG = (const char*)(g_Qh + (size_t)(b * SEQ + q0) * HID);
    const char* QlG = (const char*)(g_Ql + (size_t)(b * SEQ + q0) * HID);
    const char* KhG = (const char*)(g_Kh + (size_t)(b * SEQ + k0) * HID);
    const char* KlG = (const char*)(g_Kl + (size_t)(b * SEQ + k0) * HID);

    auto loadchunk = [&](int c) {
        uint32_t base = sm32 + (c & 1) * SG_STG;
        #pragma unroll
        for (int e = 0; e < 2; e++) {
            int idx = e * 256 + tid;
            int row = idx >> 2, col = idx & 3;
            uint32_t so = row * 80 + col * 16;
            size_t   go = (size_t)row * 512 + c * 64 + col * 16;
            CPA(base + SG_QH + so, QhG + go);
            CPA(base + SG_QL + so, QlG + go);
            CPA(base + SG_KH + so, KhG + go);
            CPA(base + SG_KL + so, KlG + go);
        }
    };

    float c[2][8][4];
    #pragma unroll
    for (int m = 0; m < 2; m++)
        #pragma unroll
        for (int n = 0; n < 8; n++)
            #pragma unroll
            for (int j = 0; j < 4; j++) c[m][n][j] = 0.0f;

    const uint32_t a_roff = (uint32_t)((lane & 7) + ((lane & 8) ? 8 : 0)) * 80
                          + ((lane & 16) ? 16 : 0);
    const uint32_t b_roff = (uint32_t)((lane & 7) + ((lane & 16) ? 8 : 0)) * 80
                          + ((lane & 8) ? 16 : 0);

    loadchunk(0);
    CP_COMMIT();
    for (int ch = 0; ch < 8; ch++) {
        CP_WAIT(0);
        __syncthreads();
        if (ch + 1 < 8) { loadchunk(ch + 1); CP_COMMIT(); }
        const uint32_t base = sm32 + (ch & 1) * SG_STG;
        #pragma unroll
        for (int kk = 0; kk < 2; kk++) {
            uint32_t ah[2][4], al[2][4];
            #pragma unroll
            for (int m = 0; m < 2; m++) {
                uint32_t arow = (uint32_t)(mw * 32 + m * 16) * 80 + kk * 32;
                LDSM4(ah[m], base + SG_QH + arow + a_roff);
                LDSM4(al[m], base + SG_QL + arow + a_roff);
            }
            uint32_t bh[8][2], bl[8][2];
            #pragma unroll
            for (int nn = 0; nn < 4; nn++) {
                uint32_t brow = (uint32_t)(dw * 64 + nn * 16) * 80 + kk * 32;
                uint32_t r4[4];
                LDSM4(r4, base + SG_KH + brow + b_roff);
                bh[nn * 2][0] = r4[0]; bh[nn * 2][1] = r4[1];
                bh[nn * 2 + 1][0] = r4[2]; bh[nn * 2 + 1][1] = r4[3];
                LDSM4(r4, base + SG_KL + brow + b_roff);
                bl[nn * 2][0] = r4[0]; bl[nn * 2][1] = r4[1];
                bl[nn * 2 + 1][0] = r4[2]; bl[nn * 2 + 1][1] = r4[3];
            }
            #pragma unroll
            for (int m = 0; m < 2; m++)
                #pragma unroll
                for (int n = 0; n < 8; n++) {
                    mma_bf16(c[m][n], ah[m], bh[n][0], bh[n][1]);
                    mma_bf16(c[m][n], ah[m], bl[n][0], bl[n][1]);
                    mma_bf16(c[m][n], al[m], bh[n][0], bh[n][1]);
                }
        }
    }

    const int qr = lane >> 2;
    const int cg = lane & 3;
    #pragma unroll
    for (int m = 0; m < 2; m++) {
        float mx0 = c[m][0][0], mx1 = c[m][0][2];
        #pragma unroll
        for (int n = 0; n < 8; n++) {
            mx0 = fmaxf(mx0, fmaxf(c[m][n][0], c[m][n][1]));
            mx1 = fmaxf(mx1, fmaxf(c[m][n][2], c[m][n][3]));
        }
        mx0 = fmaxf(mx0, __shfl_xor_sync(0xFFFFFFFF, mx0, 1));
        mx0 = fmaxf(mx0, __shfl_xor_sync(0xFFFFFFFF, mx0, 2));
        mx1 = fmaxf(mx1, __shfl_xor_sync(0xFFFFFFFF, mx1, 1));
        mx1 = fmaxf(mx1, __shfl_xor_sync(0xFFFFFFFF, mx1, 2));
        if (cg == 0) {
            atomicMax(&g_rmax[b * SEQ + q0 + mw * 32 + m * 16 + qr], enc_f(mx0));
            atomicMax(&g_rmax[b * SEQ + q0 + mw * 32 + m * 16 + qr + 8], enc_f(mx1));
        }
        float* r0 = g_S + ((size_t)b * SEQ + q0 + mw * 32 + m * 16 + qr) * SEQ + k0 + dw * 64;
        float* r1 = r0 + (size_t)8 * SEQ;
        #pragma unroll
        for (int n = 0; n < 8; n++) {
            *reinterpret_cast<float2*>(r0 + n * 8 + cg * 2) = make_float2(c[m][n][0], c[m][n][1]);
            *reinterpret_cast<float2*>(r1 + n * 8 + cg * 2) = make_float2(c[m][n][2], c[m][n][3]);
        }
    }
}

// ---------------------------------------------------------------------------
// pv_body: O = softmax(S) V, register P, 64 q rows.  (proven)
// ---------------------------------------------------------------------------
#define PV_S0    0
#define PV_S1    18432                 // S: 64 x 288 B
#define PV_V0    36864                 // V: 64 x 528 B
#define PV_V1    70656
#define PV_MS    104448                // 64 f32 rowmax
#define PV_RL    104704                // 64 f32 rowsum
#define PV_SMEM  104960
#define PV_NT    (SEQ / 64)

__device__ __forceinline__ void pv_body(char* smem, float* __restrict__ out,
                                        int b, int q0)
{
    const uint32_t sm32 = smem_u32(smem);
    const int tid = threadIdx.x;
    const int w = tid >> 5, lane = tid & 31;
    const int mw = w >> 1;
    const int nh = w & 1;
    const int qr = lane >> 2;
    const int cg = lane & 3;

    const int lrow0 = mw * 16 + qr;
    const int lrow1 = lrow0 + 8;

    const char* SG = (const char*)(g_S + ((size_t)b * SEQ + q0) * SEQ);
    const char* VG = (const char*)(g_Vh + (size_t)b * SEQ * HID);
    float* ms = (float*)(smem + PV_MS);
    float* Rl = (float*)(smem + PV_RL);

    if (tid < 64) ms[tid] = dec_f(g_rmax[b * SEQ + q0 + tid]);

    auto loadtile = [&](int kt) {
        uint32_t sb = sm32 + ((kt & 1) ? PV_S1 : PV_S0);
        uint32_t vb = sm32 + ((kt & 1) ? PV_V1 : PV_V0);
        #pragma unroll
        for (int e = 0; e < 4; e++) {
            int idx = e * 256 + tid, row = idx >> 4, col = idx & 15;
            CPA(sb + row * 288 + col * 16,
                SG + (size_t)row * (SEQ * 4) + (size_t)kt * 256 + col * 16);
        }
        #pragma unroll
        for (int e = 0; e < 8; e++) {
            int idx = e * 256 + tid, row = idx >> 5, col = idx & 31;
            CPA(vb + row * 528 + col * 16,
                VG + (size_t)(kt * 64 + row) * 512 + col * 16);
        }
    };

    float accO[16][4];
    #pragma unroll
    for (int n = 0; n < 16; n++)
        #pragma unroll
        for (int j = 0; j < 4; j++) accO[n][j] = 0.0f;
    float lp0 = 0.0f, lp1 = 0.0f;
    const float L2E = 1.44269504f;

    loadtile(0);
    CP_COMMIT();
    __syncthreads();
    const float mr0 = ms[lrow0];
    const float mr1 = ms[lrow1];

    const uint32_t s_off0 = (uint32_t)lrow0 * 288 + cg * 8;
    const uint32_t s_off1 = (uint32_t)lrow1 * 288 + cg * 8;
    const uint32_t v_lane = (uint32_t)(lane & 15) * 528
                          + (uint32_t)(nh * 128 + (lane >> 4) * 8) * 2;

    for (int kt = 0; kt < PV_NT; kt++) {
        CP_WAIT(0);
        __syncthreads();
        if (kt + 1 < PV_NT) { loadtile(kt + 1); CP_COMMIT(); }
        const uint32_t sbase = sm32 + ((kt & 1) ? PV_S1 : PV_S0);
        const uint32_t vbase = sm32 + ((kt & 1) ? PV_V1 : PV_V0);

        #pragma unroll
        for (int kk = 0; kk < 4; kk++) {
            float2 s00, s10, s01, s11;
            asm volatile("ld.shared.v2.f32 {%0,%1}, [%2];"
                : "=f"(s00.x), "=f"(s00.y) : "r"(sbase + s_off0 + kk * 64));
            asm volatile("ld.shared.v2.f32 {%0,%1}, [%2];"
                : "=f"(s10.x), "=f"(s10.y) : "r"(sbase + s_off1 + kk * 64));
            asm volatile("ld.shared.v2.f32 {%0,%1}, [%2];"
                : "=f"(s01.x), "=f"(s01.y) : "r"(sbase + s_off0 + kk * 64 + 32));
            asm volatile("ld.shared.v2.f32 {%0,%1}, [%2];"
                : "=f"(s11.x), "=f"(s11.y) : "r"(sbase + s_off1 + kk * 64 + 32));
            __half2 h0 = __floats2half2_rn(exp2f((s00.x - mr0) * L2E), exp2f((s00.y - mr0) * L2E));
            __half2 h1 = __floats2half2_rn(exp2f((s10.x - mr1) * L2E), exp2f((s10.y - mr1) * L2E));
            __half2 h2 = __floats2half2_rn(exp2f((s01.x - mr0) * L2E), exp2f((s01.y - mr0) * L2E));
            __half2 h3 = __floats2half2_rn(exp2f((s11.x - mr1) * L2E), exp2f((s11.y - mr1) * L2E));
            float2 f0 = __half22float2(h0), f2 = __half22float2(h2);
            float2 f1 = __half22float2(h1), f3 = __half22float2(h3);
            lp0 += (f0.x + f0.y) + (f2.x + f2.y);
            lp1 += (f1.x + f1.y) + (f3.x + f3.y);
            uint32_t A[4] = { *reinterpret_cast<uint32_t*>(&h0),
                              *reinterpret_cast<uint32_t*>(&h1),
                              *reinterpret_cast<uint32_t*>(&h2),
                              *reinterpret_cast<uint32_t*>(&h3) };
            #pragma unroll
            for (int nb = 0; nb < 8; nb++) {
                uint32_t r4[4];
                LDSM4T(r4, vbase + (uint32_t)(kk * 16) * 528 + (uint32_t)(nb * 16) * 2 + v_lane);
                mma_fp16(accO[nb * 2],     A, r4[0], r4[1]);
                mma_fp16(accO[nb * 2 + 1], A, r4[2], r4[3]);
            }
        }
    }

    lp0 += __shfl_xor_sync(0xFFFFFFFF, lp0, 1);
    lp0 += __shfl_xor_sync(0xFFFFFFFF, lp0, 2);
    lp1 += __shfl_xor_sync(0xFFFFFFFF, lp1, 1);
    lp1 += __shfl_xor_sync(0xFFFFFFFF, lp1, 2);
    if (nh == 0 && cg == 0) { Rl[lrow0] = lp0; Rl[lrow1] = lp1; }
    __syncthreads();
    const float li0 = 1.0f / Rl[lrow0];
    const float li1 = 1.0f / Rl[lrow1];

    float* o0 = out + ((size_t)b * SEQ + q0 + lrow0) * HID + nh * 128 + cg * 2;
    float* o1 = out + ((size_t)b * SEQ + q0 + lrow1) * HID + nh * 128 + cg * 2;
    #pragma unroll
    for (int n = 0; n < 16; n++) {
        *reinterpret_cast<float2*>(o0 + n * 8) = make_float2(accO[n][0] * li0, accO[n][1] * li0);
        *reinterpret_cast<float2*>(o1 + n * 8) = make_float2(accO[n][2] * li1, accO[n][3] * li1);
    }
}

// ---------------------------------------------------------------------------
// Kernel wrappers + combo (pv batch b_pv overlapped with s_gemm batch b_s)
// ---------------------------------------------------------------------------
__global__ __launch_bounds__(256, 2) void s_gemm_k(int b)
{
    extern __shared__ __align__(1024) char smem[];
    s_body(smem, b, blockIdx.y * 128, blockIdx.x * 128);
}

__global__ __launch_bounds__(256, 2) void pv_k(float* __restrict__ out, int b)
{
    extern __shared__ __align__(1024) char smem[];
    pv_body(smem, out, b, blockIdx.x * 64);
}

__global__ __launch_bounds__(256, 2) void combo(float* __restrict__ out,
                                                int b_pv, int b_s)
{
    extern __shared__ __align__(1024) char smem[];
    if (blockIdx.x < 64) {
        pv_body(smem, out, b_pv, blockIdx.x * 64);
    } else {
        int i = blockIdx.x - 64;
        s_body(smem, b_s, (i >> 5) * 128, (i & 31) * 128);
    }
}

// ---------------------------------------------------------------------------
extern "C" void kernel_launch(void* const* d_in, const int* in_sizes, int n_in,
                              void* d_out, int out_size)
{
    const float* X  = (const float*)d_in[0];
    const float* Wq = (const float*)d_in[1];
    const float* Wk = (const float*)d_in[2];
    const float* Wv = (const float*)d_in[3];
    // d_in[4] = lengths (unused by the reference module)
    float* out = (float*)d_out;

    cudaFuncSetAttribute(qkv_tc,  cudaFuncAttributeMaxDynamicSharedMemorySize, QT_SMEM);
    cudaFuncSetAttribute(s_gemm_k, cudaFuncAttributeMaxDynamicSharedMemorySize, SG_SMEM);
    cudaFuncSetAttribute(pv_k,    cudaFuncAttributeMaxDynamicSharedMemorySize, PV_SMEM);
    cudaFuncSetAttribute(combo,   cudaFuncAttributeMaxDynamicSharedMemorySize, PV_SMEM);

    prep_x<<<MTOT * HID / 1024, 256>>>(X);
    prep_w<<<dim3(HID, 3), 256>>>(Wq, Wk, Wv);
    qkv_tc<<<dim3(MTOT / 128, 6), 256, QT_SMEM>>>();
    s_gemm_k<<<dim3(32, 32), 256, SG_SMEM>>>(0);
    combo<<<64 + 1024, 256, PV_SMEM>>>(out, 0, 1);
    combo<<<64 + 1024, 256, PV_SMEM>>>(out, 1, 2);
    combo<<<64 + 1024, 256, PV_SMEM>>>(out, 2, 3);
    pv_k<<<64, 256, PV_SMEM>>>(out, 3);
}

// round 17
// speedup vs baseline: 1.3548x; 1.3548x over previous
#include <cuda_runtime.h>
#include <cuda_bf16.h>
#include <cuda_fp16.h>
#include <mma.h>
#include <cstdint>
using namespace nvcuda;

#define BATCH 4
#define SEQ   4096
#define HID   256
#define MTOT  (BATCH * SEQ)

__device__ __align__(16) __nv_bfloat16 g_Qh[MTOT * HID];
__device__ __align__(16) __nv_bfloat16 g_Ql[MTOT * HID];
__device__ __align__(16) __nv_bfloat16 g_Kh[MTOT * HID];
__device__ __align__(16) __nv_bfloat16 g_Kl[MTOT * HID];
__device__ __align__(16) __half        g_Vh[MTOT * HID];
__device__ __align__(16) float         g_S [(size_t)BATCH * SEQ * SEQ];   // 256 MB
__device__ __align__(16) __nv_bfloat16 g_Xh[MTOT * HID];
__device__ __align__(16) __nv_bfloat16 g_Xl[MTOT * HID];
__device__ __align__(16) __nv_bfloat16 g_Wth[3 * HID * HID];   // [z][n][k]
__device__ __align__(16) __nv_bfloat16 g_Wtl[3 * HID * HID];
__device__ unsigned g_rmax[MTOT];

__device__ __forceinline__ uint32_t smem_u32(const void* p) {
    uint32_t a;
    asm("{ .reg .u64 t; cvta.to.shared.u64 t, %1; cvt.u32.u64 %0, t; }" : "=r"(a) : "l"(p));
    return a;
}
__device__ __forceinline__ unsigned enc_f(float f) {
    unsigned u = __float_as_uint(f);
    return (u & 0x80000000u) ? ~u : (u | 0x80000000u);
}
__device__ __forceinline__ float dec_f(unsigned e) {
    unsigned u = (e & 0x80000000u) ? (e ^ 0x80000000u) : ~e;
    return __uint_as_float(u);
}
#define CPA(dst, src) \
    asm volatile("cp.async.cg.shared.global [%0], [%1], 16;" :: "r"(dst), "l"(src))
#define CP_COMMIT() asm volatile("cp.async.commit_group;" ::: "memory")
#define CP_WAIT(n)  asm volatile("cp.async.wait_group %0;" :: "n"(n) : "memory")

#define LDSM4(r, a) \
    asm volatile("ldmatrix.sync.aligned.m8n8.x4.shared.b16 {%0,%1,%2,%3}, [%4];" \
        : "=r"((r)[0]), "=r"((r)[1]), "=r"((r)[2]), "=r"((r)[3]) : "r"(a))
#define LDSM4T(r, a) \
    asm volatile("ldmatrix.sync.aligned.m8n8.x4.trans.shared.b16 {%0,%1,%2,%3}, [%4];" \
        : "=r"((r)[0]), "=r"((r)[1]), "=r"((r)[2]), "=r"((r)[3]) : "r"(a))

__device__ __forceinline__ void mma_bf16(float* c, const uint32_t* a, uint32_t b0, uint32_t b1) {
    asm volatile(
        "mma.sync.aligned.m16n8k16.row.col.f32.bf16.bf16.f32 "
        "{%0,%1,%2,%3}, {%4,%5,%6,%7}, {%8,%9}, {%0,%1,%2,%3};"
        : "+f"(c[0]), "+f"(c[1]), "+f"(c[2]), "+f"(c[3])
        : "r"(a[0]), "r"(a[1]), "r"(a[2]), "r"(a[3]), "r"(b0), "r"(b1));
}
__device__ __forceinline__ void mma_fp16(float* c, const uint32_t* a, uint32_t b0, uint32_t b1) {
    asm volatile(
        "mma.sync.aligned.m16n8k16.row.col.f32.f16.f16.f32 "
        "{%0,%1,%2,%3}, {%4,%5,%6,%7}, {%8,%9}, {%0,%1,%2,%3};"
        : "+f"(c[0]), "+f"(c[1]), "+f"(c[2]), "+f"(c[3])
        : "r"(a[0]), "r"(a[1]), "r"(a[2]), "r"(a[3]), "r"(b0), "r"(b1));
}

// ---------------------------------------------------------------------------
// prep_x: split X -> bf16 hi/lo; zero g_rmax.
// ---------------------------------------------------------------------------
__global__ __launch_bounds__(256) void prep_x(const float* __restrict__ X)
{
    int idx = blockIdx.x * 256 + threadIdx.x;          // 1 float4 per thread
    float4 v = *reinterpret_cast<const float4*>(X + (size_t)idx * 4);
    __nv_bfloat16 h0 = __float2bfloat16_rn(v.x);
    __nv_bfloat16 h1 = __float2bfloat16_rn(v.y);
    __nv_bfloat16 h2 = __float2bfloat16_rn(v.z);
    __nv_bfloat16 h3 = __float2bfloat16_rn(v.w);
    __nv_bfloat162* H = reinterpret_cast<__nv_bfloat162*>(g_Xh + (size_t)idx * 4);
    __nv_bfloat162* L = reinterpret_cast<__nv_bfloat162*>(g_Xl + (size_t)idx * 4);
    H[0] = {h0, h1}; H[1] = {h2, h3};
    L[0] = {__float2bfloat16_rn(v.x - __bfloat162float(h0)),
            __float2bfloat16_rn(v.y - __bfloat162float(h1))};
    L[1] = {__float2bfloat16_rn(v.z - __bfloat162float(h2)),
            __float2bfloat16_rn(v.w - __bfloat162float(h3))};
    if (idx < MTOT) g_rmax[idx] = 0u;
}

// ---------------------------------------------------------------------------
// prep_w: split + transpose W -> g_Wth/g_Wtl [z][n][k].
// ---------------------------------------------------------------------------
__global__ __launch_bounds__(256) void prep_w(
    const float* __restrict__ Wq, const float* __restrict__ Wk,
    const float* __restrict__ Wv)
{
    const int z = blockIdx.y, k = blockIdx.x, n = threadIdx.x;
    const float* W = (z == 0) ? Wq : (z == 1) ? Wk : Wv;
    float v = W[k * HID + n];
    __nv_bfloat16 h = __float2bfloat16_rn(v);
    g_Wth[(size_t)z * HID * HID + (size_t)n * HID + k] = h;
    g_Wtl[(size_t)z * HID * HID + (size_t)n * HID + k] =
        __float2bfloat16_rn(v - __bfloat162float(h));
}

// ---------------------------------------------------------------------------
// qkv_tc: bf16x3 tensor-core QKV projection.  (round-15 proven, unchanged)
// ---------------------------------------------------------------------------
#define QT_AH    0
#define QT_AL    10240
#define QT_BH    20480
#define QT_BL    30720
#define QT_STG   40960
#define QT_SMEM  81920

__global__ __launch_bounds__(256, 2) void qkv_tc()
{
    extern __shared__ __align__(1024) char smem[];
    const uint32_t sm32 = smem_u32(smem);
    const int tid = threadIdx.x;
    const int w = tid >> 5;
    const int lane = tid & 31;
    const int mw = w >> 1, dw = w & 1;
    const int m0 = blockIdx.x * 128;
    const int z = blockIdx.y >> 1;
    const int n0 = (blockIdx.y & 1) * 128;

    const char* AhG = (const char*)(g_Xh + (size_t)m0 * HID);
    const char* AlG = (const char*)(g_Xl + (size_t)m0 * HID);
    const char* BhG = (const char*)(g_Wth + (size_t)z * HID * HID + (size_t)n0 * HID);
    const char* BlG = (const char*)(g_Wtl + (size_t)z * HID * HID + (size_t)n0 * HID);

    auto loadchunk = [&](int c) {
        uint32_t base = sm32 + (c & 1) * QT_STG;
        #pragma unroll
        for (int e = 0; e < 2; e++) {
            int idx = e * 256 + tid;
            int row = idx >> 2, col = idx & 3;
            uint32_t so = row * 80 + col * 16;
            size_t   go = (size_t)row * 512 + c * 64 + col * 16;
            CPA(base + QT_AH + so, AhG + go);
            CPA(base + QT_AL + so, AlG + go);
            CPA(base + QT_BH + so, BhG + go);
            CPA(base + QT_BL + so, BlG + go);
        }
    };

    float c[2][8][4];
    #pragma unroll
    for (int m = 0; m < 2; m++)
        #pragma unroll
        for (int n = 0; n < 8; n++)
            #pragma unroll
            for (int j = 0; j < 4; j++) c[m][n][j] = 0.0f;

    const uint32_t a_roff = (uint32_t)((lane & 7) + ((lane & 8) ? 8 : 0)) * 80
                          + ((lane & 16) ? 16 : 0);
    const uint32_t b_roff = (uint32_t)((lane & 7) + ((lane & 16) ? 8 : 0)) * 80
                          + ((lane & 8) ? 16 : 0);

    loadchunk(0);
    CP_COMMIT();
    for (int ch = 0; ch < 8; ch++) {
        CP_WAIT(0);
        __syncthreads();
        if (ch + 1 < 8) { loadchunk(ch + 1); CP_COMMIT(); }
        const uint32_t base = sm32 + (ch & 1) * QT_STG;
        #pragma unroll
        for (int kk = 0; kk < 2; kk++) {
            uint32_t ah[2][4], al[2][4];
            #pragma unroll
            for (int m = 0; m < 2; m++) {
                uint32_t arow = (uint32_t)(mw * 32 + m * 16) * 80 + kk * 32;
                LDSM4(ah[m], base + QT_AH + arow + a_roff);
                LDSM4(al[m], base + QT_AL + arow + a_roff);
            }
            uint32_t bh[8][2], bl[8][2];
            #pragma unroll
            for (int nn = 0; nn < 4; nn++) {
                uint32_t brow = (uint32_t)(dw * 64 + nn * 16) * 80 + kk * 32;
                uint32_t r4[4];
                LDSM4(r4, base + QT_BH + brow + b_roff);
                bh[nn * 2][0] = r4[0]; bh[nn * 2][1] = r4[1];
                bh[nn * 2 + 1][0] = r4[2]; bh[nn * 2 + 1][1] = r4[3];
                LDSM4(r4, base + QT_BL + brow + b_roff);
                bl[nn * 2][0] = r4[0]; bl[nn * 2][1] = r4[1];
                bl[nn * 2 + 1][0] = r4[2]; bl[nn * 2 + 1][1] = r4[3];
            }
            #pragma unroll
            for (int m = 0; m < 2; m++)
                #pragma unroll
                for (int n = 0; n < 8; n++) {
                    mma_bf16(c[m][n], ah[m], bh[n][0], bh[n][1]);
                    mma_bf16(c[m][n], ah[m], bl[n][0], bl[n][1]);
                    mma_bf16(c[m][n], al[m], bh[n][0], bh[n][1]);
                }
        }
    }

    const int qr = lane >> 2;
    const int cg = lane & 3;
    const float s = (z == 0) ? 0.0625f : 1.0f;
    #pragma unroll
    for (int m = 0; m < 2; m++) {
        int row0 = m0 + mw * 32 + m * 16 + qr;
        int colb = n0 + dw * 64 + cg * 2;
        if (z == 2) {
            #pragma unroll
            for (int rr = 0; rr < 2; rr++) {
                __half* Vr = g_Vh + (size_t)(row0 + rr * 8) * HID;
                #pragma unroll
                for (int n = 0; n < 8; n++)
                    *reinterpret_cast<__half2*>(Vr + colb + n * 8) =
                        __floats2half2_rn(c[m][n][rr * 2], c[m][n][rr * 2 + 1]);
            }
        } else {
            __nv_bfloat16* Gh = (z == 0) ? g_Qh : g_Kh;
            __nv_bfloat16* Gl = (z == 0) ? g_Ql : g_Kl;
            #pragma unroll
            for (int rr = 0; rr < 2; rr++) {
                size_t rb = (size_t)(row0 + rr * 8) * HID;
                #pragma unroll
                for (int n = 0; n < 8; n++) {
                    float v0 = c[m][n][rr * 2] * s, v1 = c[m][n][rr * 2 + 1] * s;
                    __nv_bfloat16 h0 = __float2bfloat16_rn(v0);
                    __nv_bfloat16 h1 = __float2bfloat16_rn(v1);
                    *reinterpret_cast<__nv_bfloat162*>(Gh + rb + colb + n * 8) = {h0, h1};
                    *reinterpret_cast<__nv_bfloat162*>(Gl + rb + colb + n * 8) =
                        {__float2bfloat16_rn(v0 - __bfloat162float(h0)),
                         __float2bfloat16_rn(v1 - __bfloat162float(h1))};
                }
            }
        }
    }
}

// ---------------------------------------------------------------------------
// Kernel 2: S = Q K^T (bf16 x3) + per-row max.
// NEW: 128 threads / 4 warps, warp tile 64x64 (2x2 warp grid, 128x128 CTA).
// Halves LDSM traffic per MMA (ratio 4 -> 6 MMAs per LDSM.x4).
// ---------------------------------------------------------------------------
#define SG_QH    0
#define SG_QL    10240
#define SG_KH    20480
#define SG_KL    30720
#define SG_STG   40960
#define SG_SMEM  81920

__global__ __launch_bounds__(128, 2) void s_gemm()
{
    extern __shared__ __align__(1024) char smem[];
    const uint32_t sm32 = smem_u32(smem);
    const int tid = threadIdx.x;
    const int w = tid >> 5;
    const int lane = tid & 31;
    const int mw = w >> 1, dw = w & 1;      // 2x2 warp grid, 64x64 per warp
    const int b = blockIdx.z;
    const int q0 = blockIdx.y * 128, k0 = blockIdx.x * 128;

    const char* QhG = (const char*)(g_Qh + (size_t)(b * SEQ + q0) * HID);
    const char* QlG = (const char*)(g_Ql + (size_t)(b * SEQ + q0) * HID);
    const char* KhG = (const char*)(g_Kh + (size_t)(b * SEQ + k0) * HID);
    const char* KlG = (const char*)(g_Kl + (size_t)(b * SEQ + k0) * HID);

    auto loadchunk = [&](int c) {            // 128 rows x 64 B per matrix
        uint32_t base = sm32 + (c & 1) * SG_STG;
        #pragma unroll
        for (int e = 0; e < 4; e++) {
            int idx = e * 128 + tid;
            int row = idx >> 2, col = idx & 3;
            uint32_t so = row * 80 + col * 16;
            size_t   go = (size_t)row * 512 + c * 64 + col * 16;
            CPA(base + SG_QH + so, QhG + go);
            CPA(base + SG_QL + so, QlG + go);
            CPA(base + SG_KH + so, KhG + go);
            CPA(base + SG_KL + so, KlG + go);
        }
    };

    float c[4][8][4];
    #pragma unroll
    for (int m = 0; m < 4; m++)
        #pragma unroll
        for (int n = 0; n < 8; n++)
            #pragma unroll
            for (int j = 0; j < 4; j++) c[m][n][j] = 0.0f;

    const uint32_t a_roff = (uint32_t)((lane & 7) + ((lane & 8) ? 8 : 0)) * 80
                          + ((lane & 16) ? 16 : 0);
    const uint32_t b_roff = (uint32_t)((lane & 7) + ((lane & 16) ? 8 : 0)) * 80
                          + ((lane & 8) ? 16 : 0);

    loadchunk(0);
    CP_COMMIT();
    for (int ch = 0; ch < 8; ch++) {
        CP_WAIT(0);
        __syncthreads();
        if (ch + 1 < 8) { loadchunk(ch + 1); CP_COMMIT(); }
        const uint32_t base = sm32 + (ch & 1) * SG_STG;
        #pragma unroll
        for (int kk = 0; kk < 2; kk++) {
            uint32_t ah[4][4], al[4][4];
            #pragma unroll
            for (int m = 0; m < 4; m++) {
                uint32_t arow = (uint32_t)(mw * 64 + m * 16) * 80 + kk * 32;
                LDSM4(ah[m], base + SG_QH + arow + a_roff);
                LDSM4(al[m], base + SG_QL + arow + a_roff);
            }
            uint32_t bh[8][2], bl[8][2];
            #pragma unroll
            for (int nn = 0; nn < 4; nn++) {
                uint32_t brow = (uint32_t)(dw * 64 + nn * 16) * 80 + kk * 32;
                uint32_t r4[4];
                LDSM4(r4, base + SG_KH + brow + b_roff);
                bh[nn * 2][0] = r4[0]; bh[nn * 2][1] = r4[1];
                bh[nn * 2 + 1][0] = r4[2]; bh[nn * 2 + 1][1] = r4[3];
                LDSM4(r4, base + SG_KL + brow + b_roff);
                bl[nn * 2][0] = r4[0]; bl[nn * 2][1] = r4[1];
                bl[nn * 2 + 1][0] = r4[2]; bl[nn * 2 + 1][1] = r4[3];
            }
            #pragma unroll
            for (int m = 0; m < 4; m++)
                #pragma unroll
                for (int n = 0; n < 8; n++) {
                    mma_bf16(c[m][n], ah[m], bh[n][0], bh[n][1]);
                    mma_bf16(c[m][n], ah[m], bl[n][0], bl[n][1]);
                    mma_bf16(c[m][n], al[m], bh[n][0], bh[n][1]);
                }
        }
    }

    const int qr = lane >> 2;
    const int cg = lane & 3;
    #pragma unroll
    for (int m = 0; m < 4; m++) {
        float mx0 = c[m][0][0], mx1 = c[m][0][2];
        #pragma unroll
        for (int n = 0; n < 8; n++) {
            mx0 = fmaxf(mx0, fmaxf(c[m][n][0], c[m][n][1]));
            mx1 = fmaxf(mx1, fmaxf(c[m][n][2], c[m][n][3]));
        }
        mx0 = fmaxf(mx0, __shfl_xor_sync(0xFFFFFFFF, mx0, 1));
        mx0 = fmaxf(mx0, __shfl_xor_sync(0xFFFFFFFF, mx0, 2));
        mx1 = fmaxf(mx1, __shfl_xor_sync(0xFFFFFFFF, mx1, 1));
        mx1 = fmaxf(mx1, __shfl_xor_sync(0xFFFFFFFF, mx1, 2));
        if (cg == 0) {
            atomicMax(&g_rmax[b * SEQ + q0 + mw * 64 + m * 16 + qr], enc_f(mx0));
            atomicMax(&g_rmax[b * SEQ + q0 + mw * 64 + m * 16 + qr + 8], enc_f(mx1));
        }
        float* r0 = g_S + ((size_t)b * SEQ + q0 + mw * 64 + m * 16 + qr) * SEQ + k0 + dw * 64;
        float* r1 = r0 + (size_t)8 * SEQ;
        #pragma unroll
        for (int n = 0; n < 8; n++) {
            *reinterpret_cast<float2*>(r0 + n * 8 + cg * 2) = make_float2(c[m][n][0], c[m][n][1]);
            *reinterpret_cast<float2*>(r1 + n * 8 + cg * 2) = make_float2(c[m][n][2], c[m][n][3]);
        }
    }
}

// ---------------------------------------------------------------------------
// Kernel 3: O = softmax(S) V — register P, S staged via cp.async smem.
// (round-15 proven, unchanged)
// ---------------------------------------------------------------------------
#define PV_S0    0
#define PV_S1    18432                 // S: 64 x 288 B
#define PV_V0    36864                 // V: 64 x 528 B
#define PV_V1    70656
#define PV_MS    104448                // 64 f32 rowmax
#define PV_RL    104704                // 64 f32 rowsum
#define PV_SMEM  104960
#define PV_NT    (SEQ / 64)

__global__ __launch_bounds__(256, 2) void pv(float* __restrict__ out)
{
    extern __shared__ __align__(1024) char smem[];
    const uint32_t sm32 = smem_u32(smem);
    const int tid = threadIdx.x;
    const int w = tid >> 5, lane = tid & 31;
    const int mw = w >> 1;             // 0..3 : 16-row group
    const int nh = w & 1;              // 0..1 : 128-dim half
    const int qr = lane >> 2;          // 0..7
    const int cg = lane & 3;           // quad column group
    const int b = blockIdx.y;
    const int q0 = blockIdx.x * 64;

    const int lrow0 = mw * 16 + qr;
    const int lrow1 = lrow0 + 8;

    const char* SG = (const char*)(g_S + ((size_t)b * SEQ + q0) * SEQ);
    const char* VG = (const char*)(g_Vh + (size_t)b * SEQ * HID);
    float* ms = (float*)(smem + PV_MS);
    float* Rl = (float*)(smem + PV_RL);

    if (tid < 64) ms[tid] = dec_f(g_rmax[b * SEQ + q0 + tid]);

    auto loadtile = [&](int kt) {
        uint32_t sb = sm32 + ((kt & 1) ? PV_S1 : PV_S0);
        uint32_t vb = sm32 + ((kt & 1) ? PV_V1 : PV_V0);
        #pragma unroll
        for (int e = 0; e < 4; e++) {        // S: 64 rows x 256 B
            int idx = e * 256 + tid, row = idx >> 4, col = idx & 15;
            CPA(sb + row * 288 + col * 16,
                SG + (size_t)row * (SEQ * 4) + (size_t)kt * 256 + col * 16);
        }
        #pragma unroll
        for (int e = 0; e < 8; e++) {        // V: 64 rows x 512 B (fp16)
            int idx = e * 256 + tid, row = idx >> 5, col = idx & 31;
            CPA(vb + row * 528 + col * 16,
                VG + (size_t)(kt * 64 + row) * 512 + col * 16);
        }
    };

    float accO[16][4];
    #pragma unroll
    for (int n = 0; n < 16; n++)
        #pragma unroll
        for (int j = 0; j < 4; j++) accO[n][j] = 0.0f;
    float lp0 = 0.0f, lp1 = 0.0f;
    const float L2E = 1.44269504f;

    loadtile(0);
    CP_COMMIT();
    __syncthreads();                   // ms[] visible
    const float mr0 = ms[lrow0];
    const float mr1 = ms[lrow1];

    const uint32_t s_off0 = (uint32_t)lrow0 * 288 + cg * 8;
    const uint32_t s_off1 = (uint32_t)lrow1 * 288 + cg * 8;
    const uint32_t v_lane = (uint32_t)(lane & 15) * 528
                          + (uint32_t)(nh * 128 + (lane >> 4) * 8) * 2;

    for (int kt = 0; kt < PV_NT; kt++) {
        CP_WAIT(0);
        __syncthreads();               // tile kt visible; prev reads done
        if (kt + 1 < PV_NT) { loadtile(kt + 1); CP_COMMIT(); }
        const uint32_t sbase = sm32 + ((kt & 1) ? PV_S1 : PV_S0);
        const uint32_t vbase = sm32 + ((kt & 1) ? PV_V1 : PV_V0);

        #pragma unroll
        for (int kk = 0; kk < 4; kk++) {
            float2 s00, s10, s01, s11;
            asm volatile("ld.shared.v2.f32 {%0,%1}, [%2];"
                : "=f"(s00.x), "=f"(s00.y) : "r"(sbase + s_off0 + kk * 64));
            asm volatile("ld.shared.v2.f32 {%0,%1}, [%2];"
                : "=f"(s10.x), "=f"(s10.y) : "r"(sbase + s_off1 + kk * 64));
            asm volatile("ld.shared.v2.f32 {%0,%1}, [%2];"
                : "=f"(s01.x), "=f"(s01.y) : "r"(sbase + s_off0 + kk * 64 + 32));
            asm volatile("ld.shared.v2.f32 {%0,%1}, [%2];"
                : "=f"(s11.x), "=f"(s11.y) : "r"(sbase + s_off1 + kk * 64 + 32));
            __half2 h0 = __floats2half2_rn(exp2f((s00.x - mr0) * L2E), exp2f((s00.y - mr0) * L2E));
            __half2 h1 = __floats2half2_rn(exp2f((s10.x - mr1) * L2E), exp2f((s10.y - mr1) * L2E));
            __half2 h2 = __floats2half2_rn(exp2f((s01.x - mr0) * L2E), exp2f((s01.y - mr0) * L2E));
            __half2 h3 = __floats2half2_rn(exp2f((s11.x - mr1) * L2E), exp2f((s11.y - mr1) * L2E));
            float2 f0 = __half22float2(h0), f2 = __half22float2(h2);
            float2 f1 = __half22float2(h1), f3 = __half22float2(h3);
            lp0 += (f0.x + f0.y) + (f2.x + f2.y);
            lp1 += (f1.x + f1.y) + (f3.x + f3.y);
            uint32_t A[4] = { *reinterpret_cast<uint32_t*>(&h0),
                              *reinterpret_cast<uint32_t*>(&h1),
                              *reinterpret_cast<uint32_t*>(&h2),
                              *reinterpret_cast<uint32_t*>(&h3) };
            #pragma unroll
            for (int nb = 0; nb < 8; nb++) {
                uint32_t r4[4];
                LDSM4T(r4, vbase + (uint32_t)(kk * 16) * 528 + (uint32_t)(nb * 16) * 2 + v_lane);
                mma_fp16(accO[nb * 2],     A, r4[0], r4[1]);
                mma_fp16(accO[nb * 2 + 1], A, r4[2], r4[3]);
            }
        }
    }

    lp0 += __shfl_xor_sync(0xFFFFFFFF, lp0, 1);
    lp0 += __shfl_xor_sync(0xFFFFFFFF, lp0, 2);
    lp1 += __shfl_xor_sync(0xFFFFFFFF, lp1, 1);
    lp1 += __shfl_xor_sync(0xFFFFFFFF, lp1, 2);
    if (nh == 0 && cg == 0) { Rl[lrow0] = lp0; Rl[lrow1] = lp1; }
    __syncthreads();
    const float li0 = 1.0f / Rl[lrow0];
    const float li1 = 1.0f / Rl[lrow1];

    float* o0 = out + ((size_t)b * SEQ + q0 + lrow0) * HID + nh * 128 + cg * 2;
    float* o1 = out + ((size_t)b * SEQ + q0 + lrow1) * HID + nh * 128 + cg * 2;
    #pragma unroll
    for (int n = 0; n < 16; n++) {
        *reinterpret_cast<float2*>(o0 + n * 8) = make_float2(accO[n][0] * li0, accO[n][1] * li0);
        *reinterpret_cast<float2*>(o1 + n * 8) = make_float2(accO[n][2] * li1, accO[n][3] * li1);
    }
}

// ---------------------------------------------------------------------------
extern "C" void kernel_launch(void* const* d_in, const int* in_sizes, int n_in,
                              void* d_out, int out_size)
{
    const float* X  = (const float*)d_in[0];
    const float* Wq = (const float*)d_in[1];
    const float* Wk = (const float*)d_in[2];
    const float* Wv = (const float*)d_in[3];
    // d_in[4] = lengths (unused by the reference module)
    float* out = (float*)d_out;

    cudaFuncSetAttribute(qkv_tc, cudaFuncAttributeMaxDynamicSharedMemorySize, QT_SMEM);
    cudaFuncSetAttribute(s_gemm, cudaFuncAttributeMaxDynamicSharedMemorySize, SG_SMEM);
    cudaFuncSetAttribute(pv,     cudaFuncAttributeMaxDynamicSharedMemorySize, PV_SMEM);

    prep_x<<<MTOT * HID / 1024, 256>>>(X);
    prep_w<<<dim3(HID, 3), 256>>>(Wq, Wk, Wv);
    qkv_tc<<<dim3(MTOT / 128, 6), 256, QT_SMEM>>>();
    s_gemm<<<dim3(SEQ / 128, SEQ / 128, BATCH), 128, SG_SMEM>>>();
    pv<<<dim3(SEQ / 64, BATCH), 256, PV_SMEM>>>(out);
}